// round 15
// baseline (speedup 1.0000x reference)
#include <cuda_runtime.h>
#include <cuda_fp16.h>
#include <cstdint>
#include <math.h>

// Problem dims
#define BD   8192
#define TT   8
#define EE   256
#define GG   1024          // 4*E
#define MM   20
#define ROWS (BD*MM)       // 163840
#define FSX  12
#define PRED_ELEMS (BD*MM*FSX*2)   // 3932160

// ---------------- fp16 weight arena offsets (in halves) ----------------------
#define WH_HH0  0
#define WH_IH1  262144
#define WH_HH1  524288
#define WH_VPJ  786432        // 20 x 256 x 256
#define WH_OUTW 2097152       // 20 x 256 x 256
#define WH_F1   3407872
#define WH_F2   3670016
#define WH_D1   3932160       // [dec_w1 512x256 ; sc_w1 128x256] = 640x256
#define WH_D2   4096000       // 24 x 512
#define WH_TOT  4108288

// ---------------- scratch (static device globals; no allocation) -------------
__device__ __half g_wh[WH_TOT];
__device__ __half g_h0a[BD*EE];                 // layer-0 h, parity 0
__device__ __half g_h0b[BD*EE];                 // layer-0 h, parity 1
__device__ __half g_h1a[BD*EE];                 // layer-1 h, parity 0
__device__ __half g_h1b[BD*EE];                 // layer-1 h, parity 1
__device__ __half g_ys0h[(size_t)TT*BD*EE];
__device__ __half g_ctxh[(size_t)ROWS*EE];
__device__ __half g_lnh[(size_t)ROWS*EE];
__device__ __half g_ffnh[(size_t)ROWS*1024];
__device__ __half g_sch[(size_t)ROWS*128];
__device__ __half g_xh1h[(size_t)TT*BD*GG];     // layer-1 input proj, fp16, gate-interleaved cols
__device__ __half g_attnh[(size_t)ROWS*EE];     // outproj / FFN2 outputs (fp16)
__device__ float  g_c0[BD*EE];
__device__ float  g_c1[BD*EE];
__device__ float  g_cbias[640];                 // [dec_b1 ; sc_b1]
__device__ float  g_bsum0[GG];                  // (b_ih0+b_hh0), gate-interleaved
__device__ float  g_bsum1[GG];                  // (b_ih1+b_hh1), gate-interleaved
__device__ float2 g_wx0[GG];                    // w_ih0 columns, gate-interleaved

// ======================= helpers ============================================
__device__ __forceinline__ uint32_t smem_u32(const void* p) {
    uint32_t a;
    asm("{ .reg .u64 t; cvta.to.shared.u64 t, %1; cvt.u32.u64 %0, t; }" : "=r"(a) : "l"(p));
    return a;
}
__device__ __forceinline__ void cp16(uint32_t dst, const void* src, bool pred) {
    int sz = pred ? 16 : 0;
    asm volatile("cp.async.ca.shared.global [%0], [%1], 16, %2;" :: "r"(dst), "l"(src), "r"(sz));
}
__device__ __forceinline__ void mma_f16(float* d, const uint32_t* a, uint32_t b0, uint32_t b1) {
    asm volatile(
        "mma.sync.aligned.m16n8k16.row.col.f32.f16.f16.f32 "
        "{%0,%1,%2,%3}, {%4,%5,%6,%7}, {%8,%9}, {%0,%1,%2,%3};"
        : "+f"(d[0]), "+f"(d[1]), "+f"(d[2]), "+f"(d[3])
        : "r"(a[0]), "r"(a[1]), "r"(a[2]), "r"(a[3]), "r"(b0), "r"(b1));
}
__device__ __forceinline__ float sigf(float x) { return 1.f / (1.f + expf(-x)); }

#define STAGES 3
#define STAGE_BYTES 32768
#define GEMM_SMEM (STAGES*STAGE_BYTES)   // 98304 (WS: 64KB B + 2x16KB A)

// =================== WS mainloop macro (B panel resident) ===================
#define WS_PROLOGUE(APTR, WPTR, LDA)                                            \
    extern __shared__ char smem[];                                              \
    const uint32_t smBase = smem_u32(smem);                                     \
    const uint32_t aBuf[2] = { smBase + 65536u, smBase + 81920u };              \
    const int tid = threadIdx.x, lane = tid & 31, wid = tid >> 5;               \
    const int wm = wid >> 1, wn = wid & 1;                                      \
    const int gq = lane >> 2, ctg = lane & 3;                                   \
    const int n0 = blockIdx.x * 128;                                            \
    const int ldRow = tid >> 3, ldU = tid & 7;                                  \
    const __half* Wb = (WPTR) + (size_t)n0 * 256;                               \
    _Pragma("unroll")                                                           \
    for (int c = 0; c < 4; c++)                                                 \
        _Pragma("unroll")                                                       \
        for (int i = 0; i < 4; i++) {                                           \
            int r = (i << 5) + ldRow;                                           \
            uint32_t d = smBase + c * 16384 + r * 128 + ((ldU ^ (r & 7)) << 4); \
            cp16(d, Wb + (size_t)r * 256 + c * 64 + ldU * 8, true);             \
        }                                                                       \
    asm volatile("cp.async.commit_group;" ::: "memory");                        \
    auto issueA = [&](int t, int kc, uint32_t buf) {                            \
        const __half* p = (APTR) + (size_t)(t * 128) * (LDA) + kc * 64 + ldU * 8;\
        _Pragma("unroll")                                                       \
        for (int i = 0; i < 4; i++) {                                           \
            int r = (i << 5) + ldRow;                                           \
            uint32_t d = buf + r * 128 + ((ldU ^ (r & 7)) << 4);                \
            cp16(d, p + (size_t)r * (LDA), true);                               \
        }                                                                       \
        asm volatile("cp.async.commit_group;" ::: "memory");                    \
    };                                                                          \
    const int Wstr = gridDim.y;                                                 \
    int nxt_t = blockIdx.y, nxt_c = 0;                                          \
    issueA(nxt_t, 0, aBuf[0]);                                                  \
    nxt_c = 1;                                                                  \
    int stage = 0;                                                              \
    const int sub = lane >> 3, rin = lane & 7;                                  \
    const int arow0 = wm * 32 + ((sub & 1) << 3) + rin;                         \
    const int auSel = sub >> 1;                                                 \
    const int brow0 = wn * 64 + ((sub >> 1) << 3) + rin;                        \
    const int buSel = sub & 1;

#define WS_TILE_MAINLOOP(MTILES)                                                \
    float acc[2][8][4];                                                         \
    _Pragma("unroll")                                                           \
    for (int i = 0; i < 2; i++)                                                 \
        _Pragma("unroll")                                                       \
        for (int j = 0; j < 8; j++)                                             \
            _Pragma("unroll")                                                   \
            for (int q = 0; q < 4; q++) acc[i][j][q] = 0.f;                     \
    _Pragma("unroll")                                                           \
    for (int kc = 0; kc < 4; kc++) {                                            \
        asm volatile("cp.async.wait_group 0;" ::: "memory");                    \
        __syncthreads();                                                        \
        if (nxt_c == 4) { nxt_c = 0; nxt_t += Wstr; }                           \
        if (nxt_t < (MTILES)) { issueA(nxt_t, nxt_c, aBuf[stage ^ 1]); nxt_c++; }\
        uint32_t aS = aBuf[stage];                                              \
        uint32_t bS = smBase + kc * 16384;                                      \
        _Pragma("unroll")                                                       \
        for (int ks = 0; ks < 4; ks++) {                                        \
            uint32_t af[2][4];                                                  \
            _Pragma("unroll")                                                   \
            for (int mtl = 0; mtl < 2; mtl++) {                                 \
                int row = arow0 + mtl * 16;                                     \
                int unit = (2 * ks + auSel) ^ (row & 7);                        \
                uint32_t addr = aS + row * 128 + (unit << 4);                   \
                asm volatile("ldmatrix.sync.aligned.m8n8.x4.shared.b16 {%0,%1,%2,%3}, [%4];" \
                    : "=r"(af[mtl][0]), "=r"(af[mtl][1]), "=r"(af[mtl][2]), "=r"(af[mtl][3]) \
                    : "r"(addr));                                               \
            }                                                                   \
            _Pragma("unroll")                                                   \
            for (int p = 0; p < 4; p++) {                                       \
                int row = brow0 + p * 16;                                       \
                int unit = (2 * ks + buSel) ^ (row & 7);                        \
                uint32_t addr = bS + row * 128 + (unit << 4);                   \
                uint32_t bf[4];                                                 \
                asm volatile("ldmatrix.sync.aligned.m8n8.x4.shared.b16 {%0,%1,%2,%3}, [%4];" \
                    : "=r"(bf[0]), "=r"(bf[1]), "=r"(bf[2]), "=r"(bf[3])        \
                    : "r"(addr));                                               \
                mma_f16(acc[0][2 * p],     af[0], bf[0], bf[1]);                \
                mma_f16(acc[0][2 * p + 1], af[0], bf[2], bf[3]);                \
                mma_f16(acc[1][2 * p],     af[1], bf[0], bf[1]);                \
                mma_f16(acc[1][2 * p + 1], af[1], bf[2], bf[3]);                \
            }                                                                   \
        }                                                                       \
        stage ^= 1;                                                             \
    }

// ======================= weight-stationary fp16 GEMM (K=256) ================
// EP: 1 fp16-out no bias | 2 fp16-out +bias(z) | 4 fp16-out +bias relu
//     5 elu +cbias split (col<512 -> Cv, else Cv2)
template<int EP>
__global__ void __launch_bounds__(256, 2)
hgemm_ws(const __half* __restrict__ A, long sA, int lda,
         const __half* __restrict__ Wt, long sW,
         const float* __restrict__ bias, long sBias,
         void* __restrict__ Cv, long sC, int ldc,
         int Mtiles, __half* __restrict__ Cv2)
{
    const __half* Ab = A + (size_t)blockIdx.z * sA;
    const __half* Wp = Wt + (size_t)blockIdx.z * sW;
    WS_PROLOGUE(Ab, Wp, lda)

    for (int t = blockIdx.y; t < Mtiles; t += Wstr) {
        WS_TILE_MAINLOOP(Mtiles)

        const float* bz = (EP == 2 || EP == 4) ? bias + (size_t)blockIdx.z * sBias : bias;
#pragma unroll
        for (int mtl = 0; mtl < 2; mtl++) {
#pragma unroll
            for (int hf = 0; hf < 2; hf++) {
                size_t r = (size_t)t * 128 + wm * 32 + mtl * 16 + gq + hf * 8;
#pragma unroll
                for (int ntl = 0; ntl < 8; ntl++) {
                    int col = n0 + wn * 64 + ntl * 8 + 2 * ctg;
                    float v0 = acc[mtl][ntl][hf * 2 + 0];
                    float v1 = acc[mtl][ntl][hf * 2 + 1];
                    if (EP == 2 || EP == 4) { v0 += __ldg(bz + col); v1 += __ldg(bz + col + 1); }
                    if (EP == 4) { v0 = v0 > 0.f ? v0 : 0.f; v1 = v1 > 0.f ? v1 : 0.f; }
                    if (EP == 5) {
                        v0 += __ldg(bias + col); v1 += __ldg(bias + col + 1);
                        v0 = v0 > 0.f ? v0 : expm1f(v0);
                        v1 = v1 > 0.f ? v1 : expm1f(v1);
                        __half2 h = __floats2half2_rn(v0, v1);
                        if (col < 512)
                            *(__half2*)((__half*)Cv + r * 512 + col) = h;
                        else
                            *(__half2*)(Cv2 + r * 128 + (col - 512)) = h;
                    } else {
                        __half2 h = __floats2half2_rn(v0, v1);
                        *(__half2*)((__half*)Cv + (size_t)blockIdx.z * sC + r * (size_t)ldc + col) = h;
                    }
                }
            }
        }
    }
}

// ============== fused LSTM step: WS GEMM (gate-interleaved) + cell ==========
// Ping-pong: reads h_prev from A, writes new h into hout (different buffer).
// c is updated in place (each (r,e) touched by exactly one thread).
template<int LAYER>
__global__ void __launch_bounds__(256, 2)
hgemm_ws_lstm(const __half* __restrict__ A,      // h_prev fp16 [BD][256]
              const __half* __restrict__ Wt,     // whh interleaved [1024][256]
              __half* __restrict__ hout,         // h_new fp16 [BD][256]
              int tstep, const float* __restrict__ obs)
{
    WS_PROLOGUE(A, Wt, EE)
    const int Mtiles = BD / 128;     // 64

    float* cbuf = (LAYER == 0) ? g_c0 : g_c1;

    for (int t = blockIdx.y; t < Mtiles; t += Wstr) {
        WS_TILE_MAINLOOP(Mtiles)

#pragma unroll
        for (int mtl = 0; mtl < 2; mtl++) {
#pragma unroll
            for (int hf = 0; hf < 2; hf++) {
                size_t r = (size_t)t * 128 + wm * 32 + mtl * 16 + gq + hf * 8;
                float x0 = 0.f, x1 = 0.f;
                const __half* xrow = nullptr;
                if (LAYER == 0) {
                    float2 xv = *(const float2*)(obs + (r * TT + tstep) * 2);
                    x0 = xv.x; x1 = xv.y;
                } else {
                    xrow = g_xh1h + ((size_t)tstep * BD + r) * GG;
                }
#pragma unroll
                for (int ntl = 0; ntl < 8; ntl++) {
                    int col = n0 + wn * 64 + ntl * 8 + 2 * ctg;
                    float v0 = acc[mtl][ntl][hf * 2 + 0];
                    float v1 = acc[mtl][ntl][hf * 2 + 1];
                    if (LAYER == 0) {
                        float2 w0 = g_wx0[col], w1 = g_wx0[col + 1];
                        v0 += g_bsum0[col]     + x0 * w0.x + x1 * w0.y;
                        v1 += g_bsum0[col + 1] + x0 * w1.x + x1 * w1.y;
                    } else {
                        __half2 xh = *(const __half2*)(xrow + col);
                        float2 xf = __half22float2(xh);
                        v0 += g_bsum1[col]     + xf.x;
                        v1 += g_bsum1[col + 1] + xf.y;
                    }
                    float o0 = __shfl_xor_sync(0xffffffffu, v0, 1);
                    float o1 = __shfl_xor_sync(0xffffffffu, v1, 1);
                    if ((ctg & 1) == 0) {
                        // this thread: (i,f) = (v0,v1); partner: (g,o) = (o0,o1)
                        int e = col >> 2;
                        float ig = sigf(v0), fg = sigf(v1);
                        float gg = tanhf(o0), og = sigf(o1);
                        size_t ci = r * EE + e;
                        float cn = fg * cbuf[ci] + ig * gg;
                        float hn = og * tanhf(cn);
                        cbuf[ci] = cn;
                        __half hh = __float2half(hn);
                        hout[ci] = hh;
                        if (LAYER == 0)
                            g_ys0h[(size_t)tstep * BD * EE + ci] = hh;
                    }
                }
            }
        }
    }
}

// -------- t=0 LSTM step: h=0 => gates = bias + x-term only (no GEMM) --------
template<int LAYER>
__global__ void lstm_first(const float* __restrict__ obs, __half* __restrict__ hout)
{
    int idx = blockIdx.x * blockDim.x + threadIdx.x;
    if (idx >= BD * EE) return;
    int b = idx >> 8, e = idx & 255;
    int j4 = e << 2;
    float g[4];
    if (LAYER == 0) {
        float2 xv = *(const float2*)(obs + ((size_t)b * TT) * 2);
#pragma unroll
        for (int q = 0; q < 4; q++) {
            float2 w = g_wx0[j4 + q];
            g[q] = g_bsum0[j4 + q] + xv.x * w.x + xv.y * w.y;
        }
    } else {
        const __half* xr = g_xh1h + (size_t)b * GG;   // t = 0
#pragma unroll
        for (int q = 0; q < 4; q++)
            g[q] = g_bsum1[j4 + q] + __half2float(xr[j4 + q]);
    }
    float ig = sigf(g[0]), gg = tanhf(g[2]), og = sigf(g[3]);
    float cn = ig * gg;                    // c_prev = 0
    float hn = og * tanhf(cn);
    __half hh = __float2half(hn);
    if (LAYER == 0) {
        g_c0[idx] = cn; hout[idx] = hh; g_ys0h[idx] = hh;
    } else {
        g_c1[idx] = cn; hout[idx] = hh;
    }
}

// ======================= generic fp16 GEMM (K=512/1024 paths) ===============
template<int ACT, int OUTH>
__global__ void __launch_bounds__(256, 2)
hgemm(const __half* __restrict__ A, long sA, int lda,
      const __half* __restrict__ W, long sW,
      const float* __restrict__ bias, long sBias,
      void* __restrict__ Cv, long sC, int ldc,
      int Nreal, int K, const float* __restrict__ obs)
{
    extern __shared__ char smem[];
    const uint32_t smBase = smem_u32(smem);

    const int tid = threadIdx.x, lane = tid & 31, wid = tid >> 5;
    const int wm = wid >> 1, wn = wid & 1;
    const int gq = lane >> 2, ctg = lane & 3;

    const __half* Ab = A + (size_t)blockIdx.z * sA;
    const __half* Wb = W + (size_t)blockIdx.z * sW;
    const size_t row0 = (size_t)blockIdx.y * 128;
    const int    n0   = blockIdx.x * 128;
    const int    nk   = K >> 6;

    const int ldRow = tid >> 3;
    const int ldU   = tid & 7;

    auto issue = [&](int kc, int stage) {
        uint32_t aS = smBase + stage * STAGE_BYTES;
        uint32_t bS = aS + 16384;
        int kt = kc << 6;
#pragma unroll
        for (int i = 0; i < 4; i++) {
            int r = (i << 5) + ldRow;
            uint32_t d = aS + r * 128 + ((ldU ^ (r & 7)) << 4);
            cp16(d, Ab + (row0 + r) * (size_t)lda + kt + (ldU << 3), true);
        }
#pragma unroll
        for (int i = 0; i < 4; i++) {
            int r = (i << 5) + ldRow;
            uint32_t d = bS + r * 128 + ((ldU ^ (r & 7)) << 4);
            cp16(d, Wb + (size_t)(n0 + r) * K + kt + (ldU << 3), (n0 + r) < Nreal);
        }
    };

    float acc[2][8][4];
#pragma unroll
    for (int i = 0; i < 2; i++)
#pragma unroll
        for (int j = 0; j < 8; j++)
#pragma unroll
            for (int q = 0; q < 4; q++) acc[i][j][q] = 0.f;

    issue(0, 0);
    asm volatile("cp.async.commit_group;" ::: "memory");
    if (nk > 1) issue(1, 1);
    asm volatile("cp.async.commit_group;" ::: "memory");

    const int sub = lane >> 3, rin = lane & 7;
    const int arow0 = wm * 32 + ((sub & 1) << 3) + rin;
    const int auSel = sub >> 1;
    const int brow0 = wn * 64 + ((sub >> 1) << 3) + rin;
    const int buSel = sub & 1;

    for (int kc = 0; kc < nk; kc++) {
        asm volatile("cp.async.wait_group 1;" ::: "memory");
        __syncthreads();
        if (kc + 2 < nk) issue(kc + 2, (kc + 2) % STAGES);
        asm volatile("cp.async.commit_group;" ::: "memory");

        uint32_t aS = smBase + (kc % STAGES) * STAGE_BYTES;
        uint32_t bS = aS + 16384;
#pragma unroll
        for (int ks = 0; ks < 4; ks++) {
            uint32_t af[2][4];
#pragma unroll
            for (int mtl = 0; mtl < 2; mtl++) {
                int row = arow0 + mtl * 16;
                int unit = (2 * ks + auSel) ^ (row & 7);
                uint32_t addr = aS + row * 128 + (unit << 4);
                asm volatile("ldmatrix.sync.aligned.m8n8.x4.shared.b16 {%0,%1,%2,%3}, [%4];"
                    : "=r"(af[mtl][0]), "=r"(af[mtl][1]), "=r"(af[mtl][2]), "=r"(af[mtl][3])
                    : "r"(addr));
            }
#pragma unroll
            for (int p = 0; p < 4; p++) {
                int row = brow0 + p * 16;
                int unit = (2 * ks + buSel) ^ (row & 7);
                uint32_t addr = bS + row * 128 + (unit << 4);
                uint32_t bf[4];
                asm volatile("ldmatrix.sync.aligned.m8n8.x4.shared.b16 {%0,%1,%2,%3}, [%4];"
                    : "=r"(bf[0]), "=r"(bf[1]), "=r"(bf[2]), "=r"(bf[3])
                    : "r"(addr));
                mma_f16(acc[0][2 * p],     af[0], bf[0], bf[1]);
                mma_f16(acc[0][2 * p + 1], af[0], bf[2], bf[3]);
                mma_f16(acc[1][2 * p],     af[1], bf[0], bf[1]);
                mma_f16(acc[1][2 * p + 1], af[1], bf[2], bf[3]);
            }
        }
    }

    const float* brow = bias ? bias + (size_t)blockIdx.z * sBias : nullptr;
#pragma unroll
    for (int mtl = 0; mtl < 2; mtl++) {
#pragma unroll
        for (int half_ = 0; half_ < 2; half_++) {
            size_t r = row0 + wm * 32 + mtl * 16 + gq + half_ * 8;
#pragma unroll
            for (int ntl = 0; ntl < 8; ntl++) {
                int col = n0 + wn * 64 + ntl * 8 + 2 * ctg;
                if (col >= Nreal) continue;
                float v0 = acc[mtl][ntl][half_ * 2 + 0];
                float v1 = acc[mtl][ntl][half_ * 2 + 1];
                if (brow) { v0 += __ldg(brow + col); v1 += __ldg(brow + col + 1); }
                if (ACT == 3) {
                    const float* ob = obs + (r / MM) * (TT * 2) + (TT - 1) * 2;
                    v0 += __ldg(ob + (col & 1));
                    v1 += __ldg(ob + ((col + 1) & 1));
                }
                if (OUTH) {
                    __half2 h = __floats2half2_rn(v0, v1);
                    *(__half2*)((__half*)Cv + (size_t)blockIdx.z * sC + r * (size_t)ldc + col) = h;
                } else {
                    *(float2*)((float*)Cv + (size_t)blockIdx.z * sC + r * (size_t)ldc + col) = make_float2(v0, v1);
                }
            }
        }
    }
}

// ---------------- conversion & prep kernels ----------------------------------
struct Cvt6 {
    const float* s[6];
    __half* d[6];
    int n4[6];
};

__global__ void cvt_multi(Cvt6 p)
{
    int seg = blockIdx.y;
    const float4* src = (const float4*)p.s[seg];
    uint2* dst = (uint2*)p.d[seg];
    int n4 = p.n4[seg];
    for (int i = blockIdx.x * blockDim.x + threadIdx.x; i < n4;
         i += gridDim.x * blockDim.x) {
        float4 v = src[i];
        __half2 h0 = __floats2half2_rn(v.x, v.y);
        __half2 h1 = __floats2half2_rn(v.z, v.w);
        dst[i] = make_uint2(*(uint32_t*)&h0, *(uint32_t*)&h1);
    }
}

// permute 1024x256 weight into gate-interleaved rows (j' = 4e+q)
__global__ void cvt_perm(const float* __restrict__ src, __half* __restrict__ dst)
{
    int i = blockIdx.x * blockDim.x + threadIdx.x;
    if (i >= 1024 * 64) return;
    int jp = i >> 6, k4 = i & 63;
    int e = jp >> 2, q = jp & 3;
    float4 v = *(const float4*)(src + (size_t)(q * 256 + e) * 256 + k4 * 4);
    __half2 h0 = __floats2half2_rn(v.x, v.y);
    __half2 h1 = __floats2half2_rn(v.z, v.w);
    *(uint2*)(dst + (size_t)jp * 256 + k4 * 4) = make_uint2(*(uint32_t*)&h0, *(uint32_t*)&h1);
}

__global__ void cvt_vproj(const float* __restrict__ src, __half* __restrict__ dst)
{
    int i = blockIdx.x * blockDim.x + threadIdx.x;
    if (i >= MM * 16384) return;
    int c = i >> 14, j4 = i & 16383;
    float4 v = *(const float4*)(src + (size_t)c * (768 * EE) + j4 * 4);
    __half2 h0 = __floats2half2_rn(v.x, v.y);
    __half2 h1 = __floats2half2_rn(v.z, v.w);
    *(uint2*)(dst + (size_t)c * 65536 + j4 * 4) = make_uint2(*(uint32_t*)&h0, *(uint32_t*)&h1);
}

__global__ void prep_kernel(const float* __restrict__ b_ih0, const float* __restrict__ b_hh0,
                            const float* __restrict__ b_ih1, const float* __restrict__ b_hh1,
                            const float* __restrict__ w_ih0,
                            const float* __restrict__ dec_b1, const float* __restrict__ sc_b1)
{
    int jp = blockIdx.x * blockDim.x + threadIdx.x;
    if (jp < GG) {
        int e = jp >> 2, q = jp & 3;
        int j = q * 256 + e;
        g_bsum0[jp] = b_ih0[j] + b_hh0[j];
        g_bsum1[jp] = b_ih1[j] + b_hh1[j];
        g_wx0[jp] = make_float2(w_ih0[2 * j], w_ih0[2 * j + 1]);
    }
    if (jp < 512) g_cbias[jp] = dec_b1[jp];
    else if (jp < 640) g_cbias[jp] = sc_b1[jp - 512];
}

// LayerNorm over E=256 (fp16 in -> fp16 out, fp32 math)
__global__ void ln_kernel_h(const __half* __restrict__ x, const float* __restrict__ gam,
                            const float* __restrict__ bet, __half* __restrict__ y)
{
    size_t warp = ((size_t)blockIdx.x * blockDim.x + threadIdx.x) >> 5;
    int lane = threadIdx.x & 31;
    if (warp >= (size_t)ROWS) return;
    uint4 raw = *(const uint4*)(x + warp * EE + lane * 8);
    __half2* hp = (__half2*)&raw;
    float v[8];
#pragma unroll
    for (int i = 0; i < 4; i++) {
        float2 f = __half22float2(hp[i]);
        v[2 * i] = f.x; v[2 * i + 1] = f.y;
    }
    float s = 0.f, sq = 0.f;
#pragma unroll
    for (int i = 0; i < 8; i++) { s += v[i]; sq += v[i] * v[i]; }
#pragma unroll
    for (int o = 16; o; o >>= 1) {
        s  += __shfl_xor_sync(0xffffffffu, s,  o);
        sq += __shfl_xor_sync(0xffffffffu, sq, o);
    }
    float m   = s * (1.f / EE);
    float var = sq * (1.f / EE) - m * m;
    float inv = rsqrtf(var + 1e-5f);
    __half2 o4[4];
#pragma unroll
    for (int i = 0; i < 4; i++) {
        int e = lane * 8 + 2 * i;
        float a0 = (v[2 * i]     - m) * inv * gam[e]     + bet[e];
        float a1 = (v[2 * i + 1] - m) * inv * gam[e + 1] + bet[e + 1];
        o4[i] = __floats2half2_rn(a0, a1);
    }
    *(uint4*)(y + warp * EE + lane * 8) = *(uint4*)o4;
}

__global__ void sc2_kernel(const __half* __restrict__ s, const float* __restrict__ w,
                           const float* __restrict__ b2, float* __restrict__ outp)
{
    size_t gwarp = ((size_t)blockIdx.x * blockDim.x + threadIdx.x) >> 5;
    int lane = threadIdx.x & 31;
    if (gwarp >= (size_t)ROWS) return;
    const __half2* row = (const __half2*)(s + gwarp * 128);
    __half2 h0 = row[lane * 2], h1 = row[lane * 2 + 1];
    float2 f0 = __half22float2(h0), f1 = __half22float2(h1);
    float4 ww = *(const float4*)(w + lane * 4);
    float acc = f0.x * ww.x + f0.y * ww.y + f1.x * ww.z + f1.y * ww.w;
#pragma unroll
    for (int o = 16; o; o >>= 1) acc += __shfl_xor_sync(0xffffffffu, acc, o);
    if (lane == 0) outp[gwarp] = acc + b2[0];
}

// ---------------- host-side -------------------------------------------------
static void ws_go(int ep,
                  const __half* A, long sA, int lda,
                  const __half* Wt, long sW,
                  const float* bias, long sBias,
                  void* C, long sC, int ldc,
                  int Mtiles, int ntN, int walkers, int nb, __half* C2)
{
    dim3 g(ntN, walkers, nb), b(256);
    switch (ep) {
    case 1: hgemm_ws<1><<<g,b,GEMM_SMEM>>>(A,sA,lda,Wt,sW,bias,sBias,C,sC,ldc,Mtiles,C2); break;
    case 2: hgemm_ws<2><<<g,b,GEMM_SMEM>>>(A,sA,lda,Wt,sW,bias,sBias,C,sC,ldc,Mtiles,C2); break;
    case 4: hgemm_ws<4><<<g,b,GEMM_SMEM>>>(A,sA,lda,Wt,sW,bias,sBias,C,sC,ldc,Mtiles,C2); break;
    default: hgemm_ws<5><<<g,b,GEMM_SMEM>>>(A,sA,lda,Wt,sW,bias,sBias,C,sC,ldc,Mtiles,C2); break;
    }
}

extern "C" void kernel_launch(void* const* d_in, const int* in_sizes, int n_in,
                              void* d_out, int out_size)
{
    (void)in_sizes; (void)n_in; (void)out_size;
    const float* obs       = (const float*)d_in[0];
    const float* w_ih0     = (const float*)d_in[1];
    const float* w_hh0     = (const float*)d_in[2];
    const float* b_ih0     = (const float*)d_in[3];
    const float* b_hh0     = (const float*)d_in[4];
    const float* w_ih1     = (const float*)d_in[5];
    const float* w_hh1     = (const float*)d_in[6];
    const float* b_ih1     = (const float*)d_in[7];
    const float* b_hh1     = (const float*)d_in[8];
    const float* in_proj_w = (const float*)d_in[9];
    const float* in_proj_b = (const float*)d_in[10];
    const float* out_w     = (const float*)d_in[11];
    const float* out_b     = (const float*)d_in[12];
    const float* ln1_g     = (const float*)d_in[13];
    const float* ln1_b     = (const float*)d_in[14];
    const float* ffn_w1    = (const float*)d_in[15];
    const float* ffn_b1    = (const float*)d_in[16];
    const float* ffn_w2    = (const float*)d_in[17];
    const float* ffn_b2    = (const float*)d_in[18];
    const float* ln2_g     = (const float*)d_in[19];
    const float* ln2_b     = (const float*)d_in[20];
    const float* dec_w1    = (const float*)d_in[21];
    const float* dec_b1    = (const float*)d_in[22];
    const float* dec_w2    = (const float*)d_in[23];
    const float* dec_b2    = (const float*)d_in[24];
    const float* sc_w1     = (const float*)d_in[25];
    const float* sc_b1     = (const float*)d_in[26];
    const float* sc_w2     = (const float*)d_in[27];
    const float* sc_b2     = (const float*)d_in[28];
    float* out = (float*)d_out;

    static bool attr_done = false;
    if (!attr_done) {
        cudaFuncSetAttribute(hgemm_ws<1>, cudaFuncAttributeMaxDynamicSharedMemorySize, GEMM_SMEM);
        cudaFuncSetAttribute(hgemm_ws<2>, cudaFuncAttributeMaxDynamicSharedMemorySize, GEMM_SMEM);
        cudaFuncSetAttribute(hgemm_ws<4>, cudaFuncAttributeMaxDynamicSharedMemorySize, GEMM_SMEM);
        cudaFuncSetAttribute(hgemm_ws<5>, cudaFuncAttributeMaxDynamicSharedMemorySize, GEMM_SMEM);
        cudaFuncSetAttribute(hgemm_ws_lstm<0>, cudaFuncAttributeMaxDynamicSharedMemorySize, GEMM_SMEM);
        cudaFuncSetAttribute(hgemm_ws_lstm<1>, cudaFuncAttributeMaxDynamicSharedMemorySize, GEMM_SMEM);
        cudaFuncSetAttribute(hgemm<0,1>, cudaFuncAttributeMaxDynamicSharedMemorySize, GEMM_SMEM);
        cudaFuncSetAttribute(hgemm<3,0>, cudaFuncAttributeMaxDynamicSharedMemorySize, GEMM_SMEM);
        attr_done = true;
    }

    __half *wh, *h0a, *h0b, *h1a, *h1b, *ys0h, *ctxh, *lnh, *ffnh, *sch, *xh1h, *attnh;
    float *cb;
    cudaGetSymbolAddress((void**)&wh,    g_wh);
    cudaGetSymbolAddress((void**)&h0a,   g_h0a);
    cudaGetSymbolAddress((void**)&h0b,   g_h0b);
    cudaGetSymbolAddress((void**)&h1a,   g_h1a);
    cudaGetSymbolAddress((void**)&h1b,   g_h1b);
    cudaGetSymbolAddress((void**)&ys0h,  g_ys0h);
    cudaGetSymbolAddress((void**)&ctxh,  g_ctxh);
    cudaGetSymbolAddress((void**)&lnh,   g_lnh);
    cudaGetSymbolAddress((void**)&ffnh,  g_ffnh);
    cudaGetSymbolAddress((void**)&sch,   g_sch);
    cudaGetSymbolAddress((void**)&xh1h,  g_xh1h);
    cudaGetSymbolAddress((void**)&attnh, g_attnh);
    cudaGetSymbolAddress((void**)&cb,    g_cbias);

    // -------- weight conversions --------
    {
        Cvt6 p;
        p.s[0] = out_w;  p.d[0] = wh + WH_OUTW; p.n4[0] = 1310720 / 4;
        p.s[1] = ffn_w1; p.d[1] = wh + WH_F1;   p.n4[1] = 262144 / 4;
        p.s[2] = ffn_w2; p.d[2] = wh + WH_F2;   p.n4[2] = 262144 / 4;
        p.s[3] = dec_w1; p.d[3] = wh + WH_D1;   p.n4[3] = 131072 / 4;
        p.s[4] = sc_w1;  p.d[4] = wh + WH_D1 + 131072; p.n4[4] = 32768 / 4;
        p.s[5] = dec_w2; p.d[5] = wh + WH_D2;   p.n4[5] = 12288 / 4;
        dim3 g(512, 6), b(256);
        cvt_multi<<<g, b>>>(p);
    }
    cvt_perm<<<(1024 * 64 + 255) / 256, 256>>>(w_hh0, wh + WH_HH0);
    cvt_perm<<<(1024 * 64 + 255) / 256, 256>>>(w_ih1, wh + WH_IH1);
    cvt_perm<<<(1024 * 64 + 255) / 256, 256>>>(w_hh1, wh + WH_HH1);
    cvt_vproj<<<(MM * 16384 + 255) / 256, 256>>>(in_proj_w + (size_t)512 * EE, wh + WH_VPJ);
    prep_kernel<<<4, 256>>>(b_ih0, b_hh0, b_ih1, b_hh1, w_ih0, dec_b1, sc_b1);

    const int PT = 256;
    const int cellBlocks = (BD * EE + PT - 1) / PT;

    // -------- LSTM layer 0 (t=0 closed-form; then fused, ping-pong h) -------
    lstm_first<0><<<cellBlocks, PT>>>(obs, h0a);            // parity 0
    {
        __half* hb[2] = { h0a, h0b };
        dim3 g(8, 32), b(256);
        for (int t = 1; t < TT; t++)
            hgemm_ws_lstm<0><<<g, b, GEMM_SMEM>>>(hb[(t - 1) & 1], wh + WH_HH0,
                                                  hb[t & 1], t, obs);
    }

    // -------- layer-1 input projections (all timesteps; interleaved cols) ---
    ws_go(1, ys0h, 0, EE, wh + WH_IH1, 0, nullptr, 0, xh1h, 0, GG, 512, 8, 37, 1, nullptr);

    // -------- LSTM layer 1 (ping-pong h; final h = parity of t=7 -> h1b) ----
    lstm_first<1><<<cellBlocks, PT>>>(nullptr, h1a);
    {
        __half* hb[2] = { h1a, h1b };
        dim3 g(8, 32), b(256);
        for (int t = 1; t < TT; t++)
            hgemm_ws_lstm<1><<<g, b, GEMM_SMEM>>>(hb[(t - 1) & 1], wh + WH_HH1,
                                                  hb[t & 1], t, nullptr);
    }
    __half* emb = h1b;   // TT-1 = 7, odd parity

    // -------- v projection (ctx = v; softmax over size-1 axis == 1) --------
    ws_go(2, emb, 0, EE, wh + WH_VPJ, 65536, in_proj_b + 512, 768,
          ctxh, EE, MM * EE, 64, 2, 7, MM, nullptr);

    // -------- per-mode output projection (fp16 out -> attnh) --------
    ws_go(2, ctxh, EE, MM * EE, wh + WH_OUTW, 65536, out_b, EE,
          attnh, EE, MM * EE, 64, 2, 7, MM, nullptr);

    // -------- LN1 -> fp16 --------
    {
        dim3 g((ROWS * 32 + 255) / 256), b(256);
        ln_kernel_h<<<g, b>>>(attnh, ln1_g, ln1_b, lnh);
    }

    // -------- FFN --------
    ws_go(4, lnh, 0, EE, wh + WH_F1, 0, ffn_b1, 0, ffnh, 0, 1024, 1280, 8, 37, 1, nullptr);
    {   // FFN2: K=1024, generic kernel, fp16 out -> attnh
        dim3 g(2, ROWS / 128, 1), b(256);
        hgemm<0,1><<<g, b, GEMM_SMEM>>>(ffnh, 0, 1024, wh + WH_F2, 0, ffn_b2, 0,
                                        attnh, 0, EE, EE, 1024, nullptr);
    }

    // -------- LN2 -> mm_emb (fp16) --------
    {
        dim3 g((ROWS * 32 + 255) / 256), b(256);
        ln_kernel_h<<<g, b>>>(attnh, ln2_g, ln2_b, lnh);
    }

    // -------- merged dec1 + sc1 (ELU, split: ffnh[512] / sch[128]) --------
    ws_go(5, lnh, 0, EE, wh + WH_D1, 0, cb, 0, ffnh, 0, 512, 1280, 5, 59, 1, sch);

    // -------- dec2 (K=512, generic; lastpos fused) --------
    {
        dim3 g(1, ROWS / 128, 1), b(256);
        hgemm<3,0><<<g, b, GEMM_SMEM>>>(ffnh, 0, 512, wh + WH_D2, 0, dec_b2, 0,
                                        out, 0, 24, 24, 512, obs);
    }

    // -------- score head final dot --------
    {
        dim3 g((ROWS * 32 + 255) / 256), b(256);
        sc2_kernel<<<g, b>>>(sch, sc_w2, sc_b2, out + PRED_ELEMS);
    }
}

// round 17
// speedup vs baseline: 1.3710x; 1.3710x over previous
#include <cuda_runtime.h>
#include <cuda_fp16.h>
#include <cstdint>
#include <math.h>

// Problem dims
#define BD   8192
#define TT   8
#define EE   256
#define GG   1024          // 4*E
#define MM   20
#define ROWS (BD*MM)       // 163840
#define FSX  12
#define PRED_ELEMS (BD*MM*FSX*2)   // 3932160

// ---------------- fp16 weight arena offsets (in halves) ----------------------
#define WH_HH0  0
#define WH_IH1  262144
#define WH_HH1  524288
#define WH_VPJ  786432        // 20 x 256 x 256
#define WH_OUTW 2097152       // 20 x 256 x 256
#define WH_F1   3407872
#define WH_F2   3670016
#define WH_D1   3932160       // [dec_w1 512x256 ; sc_w1 128x256] = 640x256
#define WH_D2   4096000       // 24 x 512
#define WH_TOT  4108288

// ---------------- scratch (static device globals; no allocation) -------------
__device__ __half g_wh[WH_TOT];
__device__ __half g_h0h[BD*EE];
__device__ __half g_h1h[BD*EE];
__device__ __half g_ys0h[(size_t)TT*BD*EE];
__device__ __half g_ctxh[(size_t)ROWS*EE];
__device__ __half g_lnh[(size_t)ROWS*EE];
__device__ __half g_ffnh[(size_t)ROWS*1024];
__device__ __half g_sch[(size_t)ROWS*128];
__device__ __half g_xh1h[(size_t)TT*BD*GG];     // layer-1 input proj, fp16
__device__ __half g_attnh[(size_t)ROWS*EE];     // outproj / FFN2 outputs (fp16)
__device__ float  g_gates[(size_t)BD*GG];
__device__ float  g_c0[BD*EE];
__device__ float  g_c1[BD*EE];
__device__ float  g_cbias[640];                 // [dec_b1 ; sc_b1]

// ======================= helpers ============================================
__device__ __forceinline__ uint32_t smem_u32(const void* p) {
    uint32_t a;
    asm("{ .reg .u64 t; cvta.to.shared.u64 t, %1; cvt.u32.u64 %0, t; }" : "=r"(a) : "l"(p));
    return a;
}
__device__ __forceinline__ void cp16(uint32_t dst, const void* src, bool pred) {
    int sz = pred ? 16 : 0;
    asm volatile("cp.async.ca.shared.global [%0], [%1], 16, %2;" :: "r"(dst), "l"(src), "r"(sz));
}
__device__ __forceinline__ void mma_f16(float* d, const uint32_t* a, uint32_t b0, uint32_t b1) {
    asm volatile(
        "mma.sync.aligned.m16n8k16.row.col.f32.f16.f16.f32 "
        "{%0,%1,%2,%3}, {%4,%5,%6,%7}, {%8,%9}, {%0,%1,%2,%3};"
        : "+f"(d[0]), "+f"(d[1]), "+f"(d[2]), "+f"(d[3])
        : "r"(a[0]), "r"(a[1]), "r"(a[2]), "r"(a[3]), "r"(b0), "r"(b1));
}
__device__ __forceinline__ float sigf(float x) { return 1.f / (1.f + expf(-x)); }

#define STAGES 3
#define STAGE_BYTES 32768
#define GEMM_SMEM (STAGES*STAGE_BYTES)   // 98304 (WS: 64KB B + 2x16KB A)

// ======================= weight-stationary fp16 GEMM (K=256) ================
// B panel (128 N x 256 K) resident in smem; CTA walks M-tiles t += gridDim.y.
// EP: 0 fp32-out no bias | 1 fp16-out no bias | 2 fp16-out +bias(z)
//     4 fp16-out +bias relu | 5 elu +cbias split (col<512 -> Cv, else Cv2)
template<int EP>
__global__ void __launch_bounds__(256, 2)
hgemm_ws(const __half* __restrict__ A, long sA, int lda,
         const __half* __restrict__ Wt, long sW,
         const float* __restrict__ bias, long sBias,
         void* __restrict__ Cv, long sC, int ldc,
         int Mtiles, __half* __restrict__ Cv2)
{
    extern __shared__ char smem[];
    const uint32_t smBase = smem_u32(smem);
    const uint32_t aBuf[2] = { smBase + 65536u, smBase + 81920u };

    const int tid = threadIdx.x, lane = tid & 31, wid = tid >> 5;
    const int wm = wid >> 1, wn = wid & 1;
    const int gq = lane >> 2, ctg = lane & 3;
    const int n0 = blockIdx.x * 128;
    const int ldRow = tid >> 3, ldU = tid & 7;

    const __half* Ab = A + (size_t)blockIdx.z * sA;
    const __half* Wb = Wt + (size_t)blockIdx.z * sW + (size_t)n0 * 256;

    // ---- load B panel once: 4 chunks x (128 rows x 64 K) ----
#pragma unroll
    for (int c = 0; c < 4; c++)
#pragma unroll
        for (int i = 0; i < 4; i++) {
            int r = (i << 5) + ldRow;
            uint32_t d = smBase + c * 16384 + r * 128 + ((ldU ^ (r & 7)) << 4);
            cp16(d, Wb + (size_t)r * 256 + c * 64 + ldU * 8, true);
        }
    asm volatile("cp.async.commit_group;" ::: "memory");

    auto issueA = [&](int t, int kc, uint32_t buf) {
        const __half* p = Ab + (size_t)(t * 128) * lda + kc * 64 + ldU * 8;
#pragma unroll
        for (int i = 0; i < 4; i++) {
            int r = (i << 5) + ldRow;
            uint32_t d = buf + r * 128 + ((ldU ^ (r & 7)) << 4);
            cp16(d, p + (size_t)r * lda, true);
        }
        asm volatile("cp.async.commit_group;" ::: "memory");
    };

    const int Wstr = gridDim.y;
    int nxt_t = blockIdx.y, nxt_c = 0;
    issueA(nxt_t, 0, aBuf[0]);
    nxt_c = 1;
    int stage = 0;

    const int sub = lane >> 3, rin = lane & 7;
    const int arow0 = wm * 32 + ((sub & 1) << 3) + rin;
    const int auSel = sub >> 1;
    const int brow0 = wn * 64 + ((sub >> 1) << 3) + rin;
    const int buSel = sub & 1;

    for (int t = blockIdx.y; t < Mtiles; t += Wstr) {
        float acc[2][8][4];
#pragma unroll
        for (int i = 0; i < 2; i++)
#pragma unroll
            for (int j = 0; j < 8; j++)
#pragma unroll
                for (int q = 0; q < 4; q++) acc[i][j][q] = 0.f;

#pragma unroll
        for (int kc = 0; kc < 4; kc++) {
            asm volatile("cp.async.wait_group 0;" ::: "memory");
            __syncthreads();
            if (nxt_c == 4) { nxt_c = 0; nxt_t += Wstr; }
            if (nxt_t < Mtiles) { issueA(nxt_t, nxt_c, aBuf[stage ^ 1]); nxt_c++; }

            uint32_t aS = aBuf[stage];
            uint32_t bS = smBase + kc * 16384;
#pragma unroll
            for (int ks = 0; ks < 4; ks++) {
                uint32_t af[2][4];
#pragma unroll
                for (int mtl = 0; mtl < 2; mtl++) {
                    int row = arow0 + mtl * 16;
                    int unit = (2 * ks + auSel) ^ (row & 7);
                    uint32_t addr = aS + row * 128 + (unit << 4);
                    asm volatile("ldmatrix.sync.aligned.m8n8.x4.shared.b16 {%0,%1,%2,%3}, [%4];"
                        : "=r"(af[mtl][0]), "=r"(af[mtl][1]), "=r"(af[mtl][2]), "=r"(af[mtl][3])
                        : "r"(addr));
                }
#pragma unroll
                for (int p = 0; p < 4; p++) {
                    int row = brow0 + p * 16;
                    int unit = (2 * ks + buSel) ^ (row & 7);
                    uint32_t addr = bS + row * 128 + (unit << 4);
                    uint32_t bf[4];
                    asm volatile("ldmatrix.sync.aligned.m8n8.x4.shared.b16 {%0,%1,%2,%3}, [%4];"
                        : "=r"(bf[0]), "=r"(bf[1]), "=r"(bf[2]), "=r"(bf[3])
                        : "r"(addr));
                    mma_f16(acc[0][2 * p],     af[0], bf[0], bf[1]);
                    mma_f16(acc[0][2 * p + 1], af[0], bf[2], bf[3]);
                    mma_f16(acc[1][2 * p],     af[1], bf[0], bf[1]);
                    mma_f16(acc[1][2 * p + 1], af[1], bf[2], bf[3]);
                }
            }
            stage ^= 1;
        }

        // ---- epilogue for tile t ----
        const float* bz = (EP == 2 || EP == 4) ? bias + (size_t)blockIdx.z * sBias : bias;
#pragma unroll
        for (int mtl = 0; mtl < 2; mtl++) {
#pragma unroll
            for (int hf = 0; hf < 2; hf++) {
                size_t r = (size_t)t * 128 + wm * 32 + mtl * 16 + gq + hf * 8;
#pragma unroll
                for (int ntl = 0; ntl < 8; ntl++) {
                    int col = n0 + wn * 64 + ntl * 8 + 2 * ctg;
                    float v0 = acc[mtl][ntl][hf * 2 + 0];
                    float v1 = acc[mtl][ntl][hf * 2 + 1];
                    if (EP == 2 || EP == 4) { v0 += __ldg(bz + col); v1 += __ldg(bz + col + 1); }
                    if (EP == 4) { v0 = v0 > 0.f ? v0 : 0.f; v1 = v1 > 0.f ? v1 : 0.f; }
                    if (EP == 5) {
                        v0 += __ldg(bias + col); v1 += __ldg(bias + col + 1);
                        v0 = v0 > 0.f ? v0 : expm1f(v0);
                        v1 = v1 > 0.f ? v1 : expm1f(v1);
                        __half2 h = __floats2half2_rn(v0, v1);
                        if (col < 512)
                            *(__half2*)((__half*)Cv + r * 512 + col) = h;
                        else
                            *(__half2*)(Cv2 + r * 128 + (col - 512)) = h;
                    } else if (EP == 0) {
                        *(float2*)((float*)Cv + (size_t)blockIdx.z * sC + r * (size_t)ldc + col)
                            = make_float2(v0, v1);
                    } else {
                        __half2 h = __floats2half2_rn(v0, v1);
                        *(__half2*)((__half*)Cv + (size_t)blockIdx.z * sC + r * (size_t)ldc + col) = h;
                    }
                }
            }
        }
    }
}

// ======================= generic fp16 GEMM (K=512/1024 paths) ===============
template<int ACT, int OUTH>
__global__ void __launch_bounds__(256, 2)
hgemm(const __half* __restrict__ A, long sA, int lda,
      const __half* __restrict__ W, long sW,
      const float* __restrict__ bias, long sBias,
      void* __restrict__ Cv, long sC, int ldc,
      int Nreal, int K, const float* __restrict__ obs)
{
    extern __shared__ char smem[];
    const uint32_t smBase = smem_u32(smem);

    const int tid = threadIdx.x, lane = tid & 31, wid = tid >> 5;
    const int wm = wid >> 1, wn = wid & 1;
    const int gq = lane >> 2, ctg = lane & 3;

    const __half* Ab = A + (size_t)blockIdx.z * sA;
    const __half* Wb = W + (size_t)blockIdx.z * sW;
    const size_t row0 = (size_t)blockIdx.y * 128;
    const int    n0   = blockIdx.x * 128;
    const int    nk   = K >> 6;

    const int ldRow = tid >> 3;
    const int ldU   = tid & 7;

    auto issue = [&](int kc, int stage) {
        uint32_t aS = smBase + stage * STAGE_BYTES;
        uint32_t bS = aS + 16384;
        int kt = kc << 6;
#pragma unroll
        for (int i = 0; i < 4; i++) {
            int r = (i << 5) + ldRow;
            uint32_t d = aS + r * 128 + ((ldU ^ (r & 7)) << 4);
            cp16(d, Ab + (row0 + r) * (size_t)lda + kt + (ldU << 3), true);
        }
#pragma unroll
        for (int i = 0; i < 4; i++) {
            int r = (i << 5) + ldRow;
            uint32_t d = bS + r * 128 + ((ldU ^ (r & 7)) << 4);
            cp16(d, Wb + (size_t)(n0 + r) * K + kt + (ldU << 3), (n0 + r) < Nreal);
        }
    };

    float acc[2][8][4];
#pragma unroll
    for (int i = 0; i < 2; i++)
#pragma unroll
        for (int j = 0; j < 8; j++)
#pragma unroll
            for (int q = 0; q < 4; q++) acc[i][j][q] = 0.f;

    issue(0, 0);
    asm volatile("cp.async.commit_group;" ::: "memory");
    if (nk > 1) issue(1, 1);
    asm volatile("cp.async.commit_group;" ::: "memory");

    const int sub = lane >> 3, rin = lane & 7;
    const int arow0 = wm * 32 + ((sub & 1) << 3) + rin;
    const int auSel = sub >> 1;
    const int brow0 = wn * 64 + ((sub >> 1) << 3) + rin;
    const int buSel = sub & 1;

    for (int kc = 0; kc < nk; kc++) {
        asm volatile("cp.async.wait_group 1;" ::: "memory");
        __syncthreads();
        if (kc + 2 < nk) issue(kc + 2, (kc + 2) % STAGES);
        asm volatile("cp.async.commit_group;" ::: "memory");

        uint32_t aS = smBase + (kc % STAGES) * STAGE_BYTES;
        uint32_t bS = aS + 16384;
#pragma unroll
        for (int ks = 0; ks < 4; ks++) {
            uint32_t af[2][4];
#pragma unroll
            for (int mtl = 0; mtl < 2; mtl++) {
                int row = arow0 + mtl * 16;
                int unit = (2 * ks + auSel) ^ (row & 7);
                uint32_t addr = aS + row * 128 + (unit << 4);
                asm volatile("ldmatrix.sync.aligned.m8n8.x4.shared.b16 {%0,%1,%2,%3}, [%4];"
                    : "=r"(af[mtl][0]), "=r"(af[mtl][1]), "=r"(af[mtl][2]), "=r"(af[mtl][3])
                    : "r"(addr));
            }
#pragma unroll
            for (int p = 0; p < 4; p++) {
                int row = brow0 + p * 16;
                int unit = (2 * ks + buSel) ^ (row & 7);
                uint32_t addr = bS + row * 128 + (unit << 4);
                uint32_t bf[4];
                asm volatile("ldmatrix.sync.aligned.m8n8.x4.shared.b16 {%0,%1,%2,%3}, [%4];"
                    : "=r"(bf[0]), "=r"(bf[1]), "=r"(bf[2]), "=r"(bf[3])
                    : "r"(addr));
                mma_f16(acc[0][2 * p],     af[0], bf[0], bf[1]);
                mma_f16(acc[0][2 * p + 1], af[0], bf[2], bf[3]);
                mma_f16(acc[1][2 * p],     af[1], bf[0], bf[1]);
                mma_f16(acc[1][2 * p + 1], af[1], bf[2], bf[3]);
            }
        }
    }

    const float* brow = bias ? bias + (size_t)blockIdx.z * sBias : nullptr;
#pragma unroll
    for (int mtl = 0; mtl < 2; mtl++) {
#pragma unroll
        for (int half_ = 0; half_ < 2; half_++) {
            size_t r = row0 + wm * 32 + mtl * 16 + gq + half_ * 8;
#pragma unroll
            for (int ntl = 0; ntl < 8; ntl++) {
                int col = n0 + wn * 64 + ntl * 8 + 2 * ctg;
                if (col >= Nreal) continue;
                float v0 = acc[mtl][ntl][half_ * 2 + 0];
                float v1 = acc[mtl][ntl][half_ * 2 + 1];
                if (brow) { v0 += __ldg(brow + col); v1 += __ldg(brow + col + 1); }
                if (ACT == 3) {
                    const float* ob = obs + (r / MM) * (TT * 2) + (TT - 1) * 2;
                    v0 += __ldg(ob + (col & 1));
                    v1 += __ldg(ob + ((col + 1) & 1));
                }
                if (OUTH) {
                    __half2 h = __floats2half2_rn(v0, v1);
                    *(__half2*)((__half*)Cv + (size_t)blockIdx.z * sC + r * (size_t)ldc + col) = h;
                } else {
                    *(float2*)((float*)Cv + (size_t)blockIdx.z * sC + r * (size_t)ldc + col) = make_float2(v0, v1);
                }
            }
        }
    }
}

// ---------------- conversion & prep kernels ----------------------------------
struct Cvt9 {
    const float* s[9];
    __half* d[9];
    int n4[9];
};

__global__ void cvt_multi(Cvt9 p)
{
    int seg = blockIdx.y;
    const float4* src = (const float4*)p.s[seg];
    uint2* dst = (uint2*)p.d[seg];
    int n4 = p.n4[seg];
    for (int i = blockIdx.x * blockDim.x + threadIdx.x; i < n4;
         i += gridDim.x * blockDim.x) {
        float4 v = src[i];
        __half2 h0 = __floats2half2_rn(v.x, v.y);
        __half2 h1 = __floats2half2_rn(v.z, v.w);
        dst[i] = make_uint2(*(uint32_t*)&h0, *(uint32_t*)&h1);
    }
}

__global__ void cvt_vproj(const float* __restrict__ src, __half* __restrict__ dst)
{
    int i = blockIdx.x * blockDim.x + threadIdx.x;
    if (i >= MM * 16384) return;
    int c = i >> 14, j4 = i & 16383;
    float4 v = *(const float4*)(src + (size_t)c * (768 * EE) + j4 * 4);
    __half2 h0 = __floats2half2_rn(v.x, v.y);
    __half2 h1 = __floats2half2_rn(v.z, v.w);
    *(uint2*)(dst + (size_t)c * 65536 + j4 * 4) = make_uint2(*(uint32_t*)&h0, *(uint32_t*)&h1);
}

__global__ void prep_cbias(const float* __restrict__ dec_b1, const float* __restrict__ sc_b1)
{
    int i = blockIdx.x * blockDim.x + threadIdx.x;
    if (i < 512) g_cbias[i] = dec_b1[i];
    else if (i < 640) g_cbias[i] = sc_b1[i - 512];
}

// -------- t=0 LSTM step: h=0, c=0 => gates = bias + x-term (no GEMM) --------
template<int LAYER>
__global__ void lstm_first(const float* __restrict__ obs, const float* __restrict__ w_ih,
                           const float* __restrict__ b_ih, const float* __restrict__ b_hh)
{
    int idx = blockIdx.x * blockDim.x + threadIdx.x;
    if (idx >= BD * EE) return;
    int b = idx >> 8, e = idx & 255;
    float g[4];
    if (LAYER == 0) {
        float2 xv = *(const float2*)(obs + ((size_t)b * TT) * 2);
#pragma unroll
        for (int q = 0; q < 4; q++) {
            int j = q * EE + e;
            g[q] = b_ih[j] + b_hh[j] + xv.x * w_ih[2 * j] + xv.y * w_ih[2 * j + 1];
        }
    } else {
        const __half* xr = g_xh1h + (size_t)b * GG;   // t = 0
#pragma unroll
        for (int q = 0; q < 4; q++) {
            int j = q * EE + e;
            g[q] = b_ih[j] + b_hh[j] + __half2float(xr[j]);
        }
    }
    float ig = sigf(g[0]), gg = tanhf(g[2]), og = sigf(g[3]);
    float cn = ig * gg;                    // c_prev = 0
    float hn = og * tanhf(cn);
    __half hh = __float2half(hn);
    if (LAYER == 0) {
        g_c0[idx] = cn; g_h0h[idx] = hh; g_ys0h[idx] = hh;
    } else {
        g_c1[idx] = cn; g_h1h[idx] = hh;
    }
}

// layer-0 LSTM cell: x-proj (K=2) fused; reads fp32 gates, writes fp16 h
__global__ void lstm_cell0(const float* __restrict__ obs, const float* __restrict__ w_ih,
                           const float* __restrict__ b_ih, const float* __restrict__ b_hh, int t)
{
    int idx = blockIdx.x * blockDim.x + threadIdx.x;
    if (idx >= BD * EE) return;
    int b = idx >> 8, e = idx & 255;
    float x0 = obs[((long)b * TT + t) * 2 + 0];
    float x1 = obs[((long)b * TT + t) * 2 + 1];
    float gv[4];
#pragma unroll
    for (int q = 0; q < 4; q++) {
        int j = q * EE + e;
        gv[q] = g_gates[(long)b * GG + j] + x0 * w_ih[2 * j] + x1 * w_ih[2 * j + 1] + b_ih[j] + b_hh[j];
    }
    float ig = sigf(gv[0]), fg = sigf(gv[1]), gg = tanhf(gv[2]), og = sigf(gv[3]);
    float cn = fg * g_c0[idx] + ig * gg;
    float hn = og * tanhf(cn);
    g_c0[idx] = cn;
    __half hh = __float2half(hn);
    g_h0h[idx] = hh;
    g_ys0h[(size_t)t * BD * EE + idx] = hh;
}

// layer-1 LSTM cell: input projection precomputed in g_xh1h (fp16)
__global__ void lstm_cell1(const float* __restrict__ b_ih, const float* __restrict__ b_hh, int t)
{
    int idx = blockIdx.x * blockDim.x + threadIdx.x;
    if (idx >= BD * EE) return;
    int b = idx >> 8, e = idx & 255;
    const __half* xh = g_xh1h + ((size_t)t * BD + b) * GG;
    float gv[4];
#pragma unroll
    for (int q = 0; q < 4; q++) {
        int j = q * EE + e;
        gv[q] = g_gates[(long)b * GG + j] + __half2float(xh[j]) + b_ih[j] + b_hh[j];
    }
    float ig = sigf(gv[0]), fg = sigf(gv[1]), gg = tanhf(gv[2]), og = sigf(gv[3]);
    float cn = fg * g_c1[idx] + ig * gg;
    float hn = og * tanhf(cn);
    g_c1[idx] = cn;
    g_h1h[idx] = __float2half(hn);
}

// LayerNorm over E=256 (fp16 in -> fp16 out, fp32 math)
__global__ void ln_kernel_h(const __half* __restrict__ x, const float* __restrict__ gam,
                            const float* __restrict__ bet, __half* __restrict__ y)
{
    size_t warp = ((size_t)blockIdx.x * blockDim.x + threadIdx.x) >> 5;
    int lane = threadIdx.x & 31;
    if (warp >= (size_t)ROWS) return;
    uint4 raw = *(const uint4*)(x + warp * EE + lane * 8);
    __half2* hp = (__half2*)&raw;
    float v[8];
#pragma unroll
    for (int i = 0; i < 4; i++) {
        float2 f = __half22float2(hp[i]);
        v[2 * i] = f.x; v[2 * i + 1] = f.y;
    }
    float s = 0.f, sq = 0.f;
#pragma unroll
    for (int i = 0; i < 8; i++) { s += v[i]; sq += v[i] * v[i]; }
#pragma unroll
    for (int o = 16; o; o >>= 1) {
        s  += __shfl_xor_sync(0xffffffffu, s,  o);
        sq += __shfl_xor_sync(0xffffffffu, sq, o);
    }
    float m   = s * (1.f / EE);
    float var = sq * (1.f / EE) - m * m;
    float inv = rsqrtf(var + 1e-5f);
    __half2 o4[4];
#pragma unroll
    for (int i = 0; i < 4; i++) {
        int e = lane * 8 + 2 * i;
        float a0 = (v[2 * i]     - m) * inv * gam[e]     + bet[e];
        float a1 = (v[2 * i + 1] - m) * inv * gam[e + 1] + bet[e + 1];
        o4[i] = __floats2half2_rn(a0, a1);
    }
    *(uint4*)(y + warp * EE + lane * 8) = *(uint4*)o4;
}

__global__ void sc2_kernel(const __half* __restrict__ s, const float* __restrict__ w,
                           const float* __restrict__ b2, float* __restrict__ outp)
{
    size_t gwarp = ((size_t)blockIdx.x * blockDim.x + threadIdx.x) >> 5;
    int lane = threadIdx.x & 31;
    if (gwarp >= (size_t)ROWS) return;
    const __half2* row = (const __half2*)(s + gwarp * 128);
    __half2 h0 = row[lane * 2], h1 = row[lane * 2 + 1];
    float2 f0 = __half22float2(h0), f1 = __half22float2(h1);
    float4 ww = *(const float4*)(w + lane * 4);
    float acc = f0.x * ww.x + f0.y * ww.y + f1.x * ww.z + f1.y * ww.w;
#pragma unroll
    for (int o = 16; o; o >>= 1) acc += __shfl_xor_sync(0xffffffffu, acc, o);
    if (lane == 0) outp[gwarp] = acc + b2[0];
}

// ---------------- host-side -------------------------------------------------
static void ws_go(int ep,
                  const __half* A, long sA, int lda,
                  const __half* Wt, long sW,
                  const float* bias, long sBias,
                  void* C, long sC, int ldc,
                  int Mtiles, int ntN, int walkers, int nb, __half* C2)
{
    dim3 g(ntN, walkers, nb), b(256);
    switch (ep) {
    case 0: hgemm_ws<0><<<g,b,GEMM_SMEM>>>(A,sA,lda,Wt,sW,bias,sBias,C,sC,ldc,Mtiles,C2); break;
    case 1: hgemm_ws<1><<<g,b,GEMM_SMEM>>>(A,sA,lda,Wt,sW,bias,sBias,C,sC,ldc,Mtiles,C2); break;
    case 2: hgemm_ws<2><<<g,b,GEMM_SMEM>>>(A,sA,lda,Wt,sW,bias,sBias,C,sC,ldc,Mtiles,C2); break;
    case 4: hgemm_ws<4><<<g,b,GEMM_SMEM>>>(A,sA,lda,Wt,sW,bias,sBias,C,sC,ldc,Mtiles,C2); break;
    default: hgemm_ws<5><<<g,b,GEMM_SMEM>>>(A,sA,lda,Wt,sW,bias,sBias,C,sC,ldc,Mtiles,C2); break;
    }
}

extern "C" void kernel_launch(void* const* d_in, const int* in_sizes, int n_in,
                              void* d_out, int out_size)
{
    (void)in_sizes; (void)n_in; (void)out_size;
    const float* obs       = (const float*)d_in[0];
    const float* w_ih0     = (const float*)d_in[1];
    const float* w_hh0     = (const float*)d_in[2];
    const float* b_ih0     = (const float*)d_in[3];
    const float* b_hh0     = (const float*)d_in[4];
    const float* w_ih1     = (const float*)d_in[5];
    const float* w_hh1     = (const float*)d_in[6];
    const float* b_ih1     = (const float*)d_in[7];
    const float* b_hh1     = (const float*)d_in[8];
    const float* in_proj_w = (const float*)d_in[9];
    const float* in_proj_b = (const float*)d_in[10];
    const float* out_w     = (const float*)d_in[11];
    const float* out_b     = (const float*)d_in[12];
    const float* ln1_g     = (const float*)d_in[13];
    const float* ln1_b     = (const float*)d_in[14];
    const float* ffn_w1    = (const float*)d_in[15];
    const float* ffn_b1    = (const float*)d_in[16];
    const float* ffn_w2    = (const float*)d_in[17];
    const float* ffn_b2    = (const float*)d_in[18];
    const float* ln2_g     = (const float*)d_in[19];
    const float* ln2_b     = (const float*)d_in[20];
    const float* dec_w1    = (const float*)d_in[21];
    const float* dec_b1    = (const float*)d_in[22];
    const float* dec_w2    = (const float*)d_in[23];
    const float* dec_b2    = (const float*)d_in[24];
    const float* sc_w1     = (const float*)d_in[25];
    const float* sc_b1     = (const float*)d_in[26];
    const float* sc_w2     = (const float*)d_in[27];
    const float* sc_b2     = (const float*)d_in[28];
    float* out = (float*)d_out;

    static bool attr_done = false;
    if (!attr_done) {
        cudaFuncSetAttribute(hgemm_ws<0>, cudaFuncAttributeMaxDynamicSharedMemorySize, GEMM_SMEM);
        cudaFuncSetAttribute(hgemm_ws<1>, cudaFuncAttributeMaxDynamicSharedMemorySize, GEMM_SMEM);
        cudaFuncSetAttribute(hgemm_ws<2>, cudaFuncAttributeMaxDynamicSharedMemorySize, GEMM_SMEM);
        cudaFuncSetAttribute(hgemm_ws<4>, cudaFuncAttributeMaxDynamicSharedMemorySize, GEMM_SMEM);
        cudaFuncSetAttribute(hgemm_ws<5>, cudaFuncAttributeMaxDynamicSharedMemorySize, GEMM_SMEM);
        cudaFuncSetAttribute(hgemm<0,1>, cudaFuncAttributeMaxDynamicSharedMemorySize, GEMM_SMEM);
        cudaFuncSetAttribute(hgemm<3,0>, cudaFuncAttributeMaxDynamicSharedMemorySize, GEMM_SMEM);
        attr_done = true;
    }

    __half *wh, *h0h, *h1h, *ys0h, *ctxh, *lnh, *ffnh, *sch, *xh1h, *attnh;
    float *gates, *cb;
    cudaGetSymbolAddress((void**)&wh,    g_wh);
    cudaGetSymbolAddress((void**)&h0h,   g_h0h);
    cudaGetSymbolAddress((void**)&h1h,   g_h1h);
    cudaGetSymbolAddress((void**)&ys0h,  g_ys0h);
    cudaGetSymbolAddress((void**)&ctxh,  g_ctxh);
    cudaGetSymbolAddress((void**)&lnh,   g_lnh);
    cudaGetSymbolAddress((void**)&ffnh,  g_ffnh);
    cudaGetSymbolAddress((void**)&sch,   g_sch);
    cudaGetSymbolAddress((void**)&xh1h,  g_xh1h);
    cudaGetSymbolAddress((void**)&attnh, g_attnh);
    cudaGetSymbolAddress((void**)&gates, g_gates);
    cudaGetSymbolAddress((void**)&cb,    g_cbias);

    // -------- weight conversions (fp32 -> fp16 arena) --------
    {
        Cvt9 p;
        p.s[0] = w_hh0;  p.d[0] = wh + WH_HH0;  p.n4[0] = 262144 / 4;
        p.s[1] = w_ih1;  p.d[1] = wh + WH_IH1;  p.n4[1] = 262144 / 4;
        p.s[2] = w_hh1;  p.d[2] = wh + WH_HH1;  p.n4[2] = 262144 / 4;
        p.s[3] = out_w;  p.d[3] = wh + WH_OUTW; p.n4[3] = 1310720 / 4;
        p.s[4] = ffn_w1; p.d[4] = wh + WH_F1;   p.n4[4] = 262144 / 4;
        p.s[5] = ffn_w2; p.d[5] = wh + WH_F2;   p.n4[5] = 262144 / 4;
        p.s[6] = dec_w1; p.d[6] = wh + WH_D1;   p.n4[6] = 131072 / 4;
        p.s[7] = sc_w1;  p.d[7] = wh + WH_D1 + 131072; p.n4[7] = 32768 / 4;
        p.s[8] = dec_w2; p.d[8] = wh + WH_D2;   p.n4[8] = 12288 / 4;
        dim3 g(512, 9), b(256);
        cvt_multi<<<g, b>>>(p);
    }
    cvt_vproj<<<(MM * 16384 + 255) / 256, 256>>>(in_proj_w + (size_t)512 * EE, wh + WH_VPJ);
    prep_cbias<<<3, 256>>>(dec_b1, sc_b1);

    const int PT = 256;
    const int cellBlocks = (BD * EE + PT - 1) / PT;

    // -------- LSTM layer 0 (t=0 closed-form; then GEMM + cell per step) -----
    lstm_first<0><<<cellBlocks, PT>>>(obs, w_ih0, b_ih0, b_hh0);
    for (int t = 1; t < TT; t++) {
        ws_go(0, h0h, 0, EE, wh + WH_HH0, 0, nullptr, 0, gates, 0, GG, 64, 8, 32, 1, nullptr);
        lstm_cell0<<<cellBlocks, PT>>>(obs, w_ih0, b_ih0, b_hh0, t);
    }

    // -------- layer-1 input projections (all timesteps; fp16 out) --------
    ws_go(1, ys0h, 0, EE, wh + WH_IH1, 0, nullptr, 0, xh1h, 0, GG, 512, 8, 37, 1, nullptr);

    // -------- LSTM layer 1 --------
    lstm_first<1><<<cellBlocks, PT>>>(nullptr, nullptr, b_ih1, b_hh1);
    for (int t = 1; t < TT; t++) {
        ws_go(0, h1h, 0, EE, wh + WH_HH1, 0, nullptr, 0, gates, 0, GG, 64, 8, 32, 1, nullptr);
        lstm_cell1<<<cellBlocks, PT>>>(b_ih1, b_hh1, t);
    }

    // -------- v projection (ctx = v; softmax over size-1 axis == 1) --------
    ws_go(2, h1h, 0, EE, wh + WH_VPJ, 65536, in_proj_b + 512, 768,
          ctxh, EE, MM * EE, 64, 2, 7, MM, nullptr);

    // -------- per-mode output projection (fp16 out -> attnh) --------
    ws_go(2, ctxh, EE, MM * EE, wh + WH_OUTW, 65536, out_b, EE,
          attnh, EE, MM * EE, 64, 2, 7, MM, nullptr);

    // -------- LN1 -> fp16 --------
    {
        dim3 g((ROWS * 32 + 255) / 256), b(256);
        ln_kernel_h<<<g, b>>>(attnh, ln1_g, ln1_b, lnh);
    }

    // -------- FFN --------
    ws_go(4, lnh, 0, EE, wh + WH_F1, 0, ffn_b1, 0, ffnh, 0, 1024, 1280, 8, 37, 1, nullptr);
    {   // FFN2: K=1024, generic kernel, fp16 out -> attnh
        dim3 g(2, ROWS / 128, 1), b(256);
        hgemm<0,1><<<g, b, GEMM_SMEM>>>(ffnh, 0, 1024, wh + WH_F2, 0, ffn_b2, 0,
                                        attnh, 0, EE, EE, 1024, nullptr);
    }

    // -------- LN2 -> mm_emb (fp16) --------
    {
        dim3 g((ROWS * 32 + 255) / 256), b(256);
        ln_kernel_h<<<g, b>>>(attnh, ln2_g, ln2_b, lnh);
    }

    // -------- merged dec1 + sc1 (ELU, split: ffnh[512] / sch[128]) --------
    ws_go(5, lnh, 0, EE, wh + WH_D1, 0, cb, 0, ffnh, 0, 512, 1280, 5, 59, 1, sch);

    // -------- dec2 (K=512, generic; lastpos fused) --------
    {
        dim3 g(1, ROWS / 128, 1), b(256);
        hgemm<3,0><<<g, b, GEMM_SMEM>>>(ffnh, 0, 512, wh + WH_D2, 0, dec_b2, 0,
                                        out, 0, 24, 24, 512, obs);
    }

    // -------- score head final dot --------
    {
        dim3 g((ROWS * 32 + 255) / 256), b(256);
        sc2_kernel<<<g, b>>>(sch, sc_w2, sc_b2, out + PRED_ELEMS);
    }
}